// round 8
// baseline (speedup 1.0000x reference)
#include <cuda_runtime.h>
#include <cstdint>

// CASSI forward: persistent work-stealing TMA pipeline + carry reduce.
//
// 444 persistent blocks (3/SM x 148). Rows popped from a device counter
// (reset kernel runs first). Each block streams its row through a 2-deep
// TMA ring (32KB tiles); the NEXT row's tiles 0-1 and ca are prefetched
// while the current row drains, so the TMA stream never bubbles.
// Reduce (proven since R6): thread tid accumulates
//   accL -> output c = t*128 + tid (terms l <= tid)
//   accH -> carry for next tile   (terms l > tid)
// carry rides in a register; no atomics, no zero-init.

#define MM   1024
#define NN   1024
#define LL   64
#define OUTC (NN + LL - 1)            // 1087
#define TN   128                      // n-rows per tile
#define TPB  128                      // threads per block
#define NTIL (NN / TN)                // 8
#define TILE_BYTES (TN * LL * 4)      // 32768
#define NBLOCKS (148 * 3)             // persistent grid
#define SMEM_DYN ((2 * TN * LL + 2 * NN) * sizeof(float))   // 73728 B

__device__ int g_ctr;

__global__ void cassi_reset_kernel() { g_ctr = 0; }

__device__ __forceinline__ uint32_t smem_u32(const void* p)
{
    uint32_t a;
    asm("{ .reg .u64 t; cvta.to.shared.u64 t, %1; cvt.u32.u64 %0, t; }"
        : "=r"(a) : "l"(p));
    return a;
}

__device__ __forceinline__ void mbar_init(uint32_t mb, uint32_t count)
{
    asm volatile("mbarrier.init.shared.b64 [%0], %1;" :: "r"(mb), "r"(count) : "memory");
}

__device__ __forceinline__ void tma_tile(uint32_t dst, const float* src, uint32_t mb)
{
    asm volatile("mbarrier.arrive.expect_tx.shared.b64 _, [%0], %1;"
                 :: "r"(mb), "r"((uint32_t)TILE_BYTES) : "memory");
    asm volatile("cp.async.bulk.shared::cta.global.mbarrier::complete_tx::bytes "
                 "[%0], [%1], %2, [%3];"
                 :: "r"(dst), "l"(src), "r"((uint32_t)TILE_BYTES), "r"(mb) : "memory");
}

__device__ __forceinline__ void mbar_wait(uint32_t mb, uint32_t parity)
{
    uint32_t done;
    asm volatile(
        "{\n\t"
        ".reg .pred p;\n\t"
        "mbarrier.try_wait.parity.acquire.cta.shared::cta.b64 p, [%1], %2;\n\t"
        "selp.b32 %0, 1, 0, p;\n\t"
        "}"
        : "=r"(done) : "r"(mb), "r"(parity) : "memory");
    if (!done) {
        asm volatile(
            "{\n\t"
            ".reg .pred P1;\n\t"
            "W%=:\n\t"
            "mbarrier.try_wait.parity.acquire.cta.shared::cta.b64 P1, [%0], %1;\n\t"
            "@P1 bra D%=;\n\t"
            "bra W%=;\n\t"
            "D%=:\n\t"
            "}"
            :: "r"(mb), "r"(parity) : "memory");
    }
}

__global__ __launch_bounds__(TPB, 3)
void cassi_persist_kernel(const float* __restrict__ x,
                          const float* __restrict__ ca,
                          float* __restrict__ y)
{
    extern __shared__ float smem[];
    float* buf[2] = { smem, smem + TN * LL };        // 32KB each
    float* sca[2] = { smem + 2 * TN * LL,
                      smem + 2 * TN * LL + NN };     // 4KB each
    __shared__ __align__(8) uint64_t mbar_store[2];
    __shared__ int s_row;

    const int tid = threadIdx.x;

    const uint32_t mb[2] = { smem_u32(&mbar_store[0]), smem_u32(&mbar_store[1]) };
    const uint32_t bs[2] = { smem_u32(buf[0]), smem_u32(buf[1]) };

    if (tid == 0) {
        mbar_init(mb[0], 1);
        mbar_init(mb[1], 1);
        s_row = atomicAdd(&g_ctr, 1);
    }
    __syncthreads();

    int cur = s_row;
    if (cur >= MM) return;

    // Prologue: stage ca[cur], issue tiles 0,1 of cur.
    #pragma unroll
    for (int i = tid; i < NN; i += TPB)
        sca[0][i] = ca[cur * NN + i];
    __syncthreads();
    if (tid == 0) {
        const float* xr = x + (size_t)cur * (NN * LL);
        tma_tile(bs[0], xr,           mb[0]);
        tma_tile(bs[1], xr + TN * LL, mb[1]);
    }

    int pp[2]  = { 0, 0 };   // next wait parity per buffer
    int bsel   = 0;          // ring position
    int cab    = 0;          // ca buffer of current row

    while (true) {
        // Pop the row after this one (prefetch target).
        if (tid == 0) s_row = atomicAdd(&g_ctr, 1);
        __syncthreads();
        const int nxt = s_row;

        const float* xcur = x + (size_t)cur * (NN * LL);
        float*       yrow = y + (size_t)cur * OUTC;
        const float* scar = sca[cab];
        float carry = 0.0f;

        #pragma unroll 1
        for (int t = 0; t < NTIL; ++t) {
            const int b = bsel;
            mbar_wait(mb[b], pp[b]);
            pp[b] ^= 1;

            const float* curbuf = buf[b];
            const float* scat   = scar + t * TN;
            float accL = carry;
            float accH = 0.0f;
            #pragma unroll
            for (int j = 0; j < LL; ++j) {
                const int  l   = (tid + j) & (LL - 1);
                const bool low = (l <= tid);
                const int  n   = low ? (tid - l) : (tid + TN - l);
                const float v  = curbuf[n * LL + l];
                if (low) accL = fmaf(v, scat[n], accL);
                else     accH = fmaf(v, scat[n], accH);
            }
            yrow[t * TN + tid] = accL;
            carry = accH;

            // Stage next row's ca while its tiles are still 2+ slots away.
            if (t == 5 && nxt < MM) {
                #pragma unroll
                for (int i = tid; i < NN; i += TPB)
                    sca[cab ^ 1][i] = ca[nxt * NN + i];
            }

            __syncthreads();   // everyone done with buf[b] (and sca staging)

            if (tid == 0) {
                if (t + 2 < NTIL) {
                    tma_tile(bs[b], xcur + (size_t)(t + 2) * TN * LL, mb[b]);
                } else if (nxt < MM) {
                    const float* xn = x + (size_t)nxt * (NN * LL);
                    tma_tile(bs[b], xn + (size_t)(t + 2 - NTIL) * TN * LL, mb[b]);
                }
            }
            bsel ^= 1;
        }

        // Tail outputs c in [NN, NN+LL-1).
        if (tid < LL - 1)
            yrow[NN + tid] = carry;

        if (nxt >= MM) break;
        cur = nxt;
        cab ^= 1;
    }
}

extern "C" void kernel_launch(void* const* d_in, const int* in_sizes, int n_in,
                              void* d_out, int out_size)
{
    const float* x  = (const float*)d_in[0];
    const float* ca = (const float*)d_in[1];
    float* y        = (float*)d_out;

    cudaFuncSetAttribute(cassi_persist_kernel,
                         cudaFuncAttributeMaxDynamicSharedMemorySize,
                         (int)SMEM_DYN);

    cassi_reset_kernel<<<1, 1>>>();
    cassi_persist_kernel<<<NBLOCKS, TPB, SMEM_DYN>>>(x, ca, y);
}

// round 9
// speedup vs baseline: 1.3702x; 1.3702x over previous
#include <cuda_runtime.h>
#include <cstdint>

// CASSI forward: R7 TMA pipeline body, half-row blocks + pinned 2 blocks/SM.
//
// Quantization math: conc = 2 blocks/SM x 148 = 296; grid = 2048 half-rows
// -> 6.92 waves -> 98.8% utilization (R7: 2.31 waves -> 77%, measured 76%).
// Each block: 4 tiles of TN=128 n-rows through a 2-deep TMA ring.
// Reduce per tile (proven since R6): accL -> c = n0+t*128+tid (l<=tid terms),
// accH -> carry (l>tid). Carry crossing the half-row split (63 cols/row) is
// resolved by atomicAdd into zero-initialized columns [512,575).

#define MM    1024
#define NN    1024
#define LL    64
#define OUTC  (NN + LL - 1)           // 1087
#define TN    128
#define TPB   128
#define HALF  512                     // n-rows per block
#define NTIL  (HALF / TN)             // 4
#define TILE_BYTES (TN * LL * 4)      // 32768
#define SMEM_PAD   102400             // pad to force 2 blocks/SM

__global__ void cassi_zero_overlap(float* __restrict__ y)
{
    // zero only the atomically-accumulated columns c in [HALF, HALF+LL-1)
    const int m = blockIdx.x;
    const int t = threadIdx.x;
    if (t < LL - 1)
        y[(size_t)m * OUTC + HALF + t] = 0.0f;
}

__device__ __forceinline__ uint32_t smem_u32(const void* p)
{
    uint32_t a;
    asm("{ .reg .u64 t; cvta.to.shared.u64 t, %1; cvt.u32.u64 %0, t; }"
        : "=r"(a) : "l"(p));
    return a;
}

__device__ __forceinline__ void mbar_init(uint32_t mb, uint32_t count)
{
    asm volatile("mbarrier.init.shared.b64 [%0], %1;" :: "r"(mb), "r"(count) : "memory");
}

__device__ __forceinline__ void tma_tile(uint32_t dst, const float* src, uint32_t mb)
{
    asm volatile("mbarrier.arrive.expect_tx.shared.b64 _, [%0], %1;"
                 :: "r"(mb), "r"((uint32_t)TILE_BYTES) : "memory");
    asm volatile("cp.async.bulk.shared::cta.global.mbarrier::complete_tx::bytes "
                 "[%0], [%1], %2, [%3];"
                 :: "r"(dst), "l"(src), "r"((uint32_t)TILE_BYTES), "r"(mb) : "memory");
}

__device__ __forceinline__ void mbar_wait(uint32_t mb, uint32_t parity)
{
    uint32_t done;
    asm volatile(
        "{\n\t"
        ".reg .pred p;\n\t"
        "mbarrier.try_wait.parity.acquire.cta.shared::cta.b64 p, [%1], %2;\n\t"
        "selp.b32 %0, 1, 0, p;\n\t"
        "}"
        : "=r"(done) : "r"(mb), "r"(parity) : "memory");
    if (!done) {
        asm volatile(
            "{\n\t"
            ".reg .pred P1;\n\t"
            "W%=:\n\t"
            "mbarrier.try_wait.parity.acquire.cta.shared::cta.b64 P1, [%0], %1;\n\t"
            "@P1 bra D%=;\n\t"
            "bra W%=;\n\t"
            "D%=:\n\t"
            "}"
            :: "r"(mb), "r"(parity) : "memory");
    }
}

__global__ __launch_bounds__(TPB)
void cassi_half_kernel(const float* __restrict__ x,
                       const float* __restrict__ ca,
                       float* __restrict__ y)
{
    extern __shared__ float smem[];
    float* buf0 = smem;                  // TN*LL floats (32KB)
    float* buf1 = smem + TN * LL;        // TN*LL floats (32KB)
    float* sca  = smem + 2 * TN * LL;    // HALF floats (2KB)
    __shared__ __align__(8) uint64_t mbar_store[2];

    const int m   = blockIdx.y;
    const int h   = blockIdx.x;          // 0 or 1
    const int n0  = h * HALF;
    const int tid = threadIdx.x;

    const float* xrow = x + ((size_t)m * NN + n0) * LL;
    float*       yrow = y + (size_t)m * OUTC;

    const uint32_t mb0 = smem_u32(&mbar_store[0]);
    const uint32_t mb1 = smem_u32(&mbar_store[1]);
    const uint32_t b0  = smem_u32(buf0);
    const uint32_t b1  = smem_u32(buf1);

    if (tid == 0) {
        mbar_init(mb0, 1);
        mbar_init(mb1, 1);
    }
    __syncthreads();

    if (tid == 0) {
        tma_tile(b0, xrow,           mb0);
        tma_tile(b1, xrow + TN * LL, mb1);
    }

    // Stage this half's ca (each tile's terms use only its own tile's ca).
    #pragma unroll
    for (int i = tid; i < HALF; i += TPB)
        sca[i] = ca[m * NN + n0 + i];
    __syncthreads();

    float carry = 0.0f;

    #pragma unroll 1
    for (int t = 0; t < NTIL; ++t) {
        const uint32_t mb     = (t & 1) ? mb1 : mb0;
        const float*   cur    = (t & 1) ? buf1 : buf0;
        const uint32_t parity = (t >> 1) & 1;

        mbar_wait(mb, parity);

        const float* scat = sca + t * TN;
        float accL = carry;              // carry == 0 for tid >= LL-1
        float accH = 0.0f;
        #pragma unroll
        for (int j = 0; j < LL; ++j) {
            const int  l   = (tid + j) & (LL - 1);
            const bool low = (l <= tid);
            const int  n   = low ? (tid - l) : (tid + TN - l);
            const float v  = cur[n * LL + l];
            if (low) accL = fmaf(v, scat[n], accL);
            else     accH = fmaf(v, scat[n], accH);
        }

        const int c = n0 + t * TN + tid;
        if (h > 0 && t == 0 && tid < LL - 1)
            atomicAdd(&yrow[c], accL);   // missing n<n0 terms come from h-1's carry
        else
            yrow[c] = accL;
        carry = accH;

        __syncthreads();                 // all threads done reading `cur`

        if (t + 2 < NTIL && tid == 0) {
            const uint32_t db = (t & 1) ? b1 : b0;
            tma_tile(db, xrow + (size_t)(t + 2) * TN * LL, mb);
        }
    }

    // Final carry: c in [n0+HALF, n0+HALF+LL-1)
    if (tid < LL - 1) {
        const int c = n0 + HALF + tid;
        if (h == 1) yrow[c] = carry;         // sole contributor (c >= NN)
        else        atomicAdd(&yrow[c], carry);
    }
}

extern "C" void kernel_launch(void* const* d_in, const int* in_sizes, int n_in,
                              void* d_out, int out_size)
{
    const float* x  = (const float*)d_in[0];
    const float* ca = (const float*)d_in[1];
    float* y        = (float*)d_out;

    cudaFuncSetAttribute(cassi_half_kernel,
                         cudaFuncAttributeMaxDynamicSharedMemorySize,
                         SMEM_PAD);

    cassi_zero_overlap<<<MM, LL>>>(y);
    cassi_half_kernel<<<dim3(2, MM), TPB, SMEM_PAD>>>(x, ca, y);
}